// round 11
// baseline (speedup 1.0000x reference)
#include <cuda_runtime.h>
#include <cuda_bf16.h>

// Inputs (metadata order):
// 0: pred float32 [2M]  1: constr_idx int32 [20M]  2: var_idx int32 [20M]
// 3: coeff float32 [20M]  4: constr_rhs float32 [1M]  5: constr_sense int32 [1M]
// Output: scalar float (mean violation)
//
// Single persistent kernel, 888 blocks (148 SMs x 6 @ 256 thr -> all
// co-resident), three phases separated by a software grid barrier:
//   P0: zero ax + out      P1: scatter (LTS-bound)      P2: reduce
// The barrier counter is monotonic across graph replays (wrap-safe compare),
// so no reset is needed and every replay does identical work.

#define MAX_CONSTRS 1000000
#define NBLOCKS     888
#define NTHREADS    256

__device__ float        g_ax[MAX_CONSTRS];
__device__ unsigned int g_bar;   // monotonic barrier counter

// ---------------------------------------------------------------------------
__device__ __forceinline__ void grid_sync() {
    __syncthreads();
    if (threadIdx.x == 0) {
        __threadfence();
        unsigned old = atomicAdd(&g_bar, 1u);
        unsigned target = old - (old % NBLOCKS) + NBLOCKS;
        unsigned cur;
        do {
            asm volatile("ld.global.acquire.gpu.u32 %0, [%1];"
                         : "=r"(cur) : "l"(&g_bar));
        } while ((int)(cur - target) < 0);
    }
    __syncthreads();
}

__device__ __forceinline__ float fast_sigmoid(float x) {
    float t;
    asm("tanh.approx.f32 %0, %1;" : "=f"(t) : "f"(0.5f * x));
    return fmaf(0.5f, t, 0.5f);
}

__device__ __forceinline__ float viol(float diff, int sn) {
    float v1 = fmaxf(diff, 0.0f);
    float v2 = fmaxf(-diff, 0.0f);
    float v3 = fabsf(diff);
    return (sn == 1) ? v1 : (sn == 2) ? v2 : (sn == 3) ? v3 : 0.0f;
}

// ---------------------------------------------------------------------------
__global__ void __launch_bounds__(NTHREADS, 6) fused_kernel(
        const float*  __restrict__ pred,
        const int4*   __restrict__ cidx4,
        const int4*   __restrict__ vidx4,
        const float4* __restrict__ coeff4,
        const float4* __restrict__ rhs4,
        const int4*   __restrict__ sense4,
        float* __restrict__ out,
        int nwork,        // nnz/4 scatter work items
        int nc4,          // n_constrs/4
        float inv_n) {
    const int tid    = blockIdx.x * NTHREADS + threadIdx.x;
    const int stride = NBLOCKS * NTHREADS;   // 227,328

    // ---- Phase 0: zero ax + out ----
    {
        float4* ax4 = reinterpret_cast<float4*>(g_ax);
        const float4 z = make_float4(0.f, 0.f, 0.f, 0.f);
        for (int i = tid; i < nc4; i += stride) ax4[i] = z;
        if (tid == 0) *out = 0.0f;
    }
    grid_sync();

    // ---- Phase 1: scatter (4 nnz per iteration) ----
    for (int i = tid; i < nwork; i += stride) {
        int4   c = __ldcs(&cidx4[i]);
        int4   v = __ldcs(&vidx4[i]);
        float4 a = __ldcs(&coeff4[i]);

        float p0 = __ldcg(&pred[v.x]);
        float p1 = __ldcg(&pred[v.y]);
        float p2 = __ldcg(&pred[v.z]);
        float p3 = __ldcg(&pred[v.w]);

        float g0 = fast_sigmoid(p0);
        float g1 = fast_sigmoid(p1);
        float g2 = fast_sigmoid(p2);
        float g3 = fast_sigmoid(p3);

        atomicAdd(&g_ax[c.x], a.x * g0);
        atomicAdd(&g_ax[c.y], a.y * g1);
        atomicAdd(&g_ax[c.z], a.z * g2);
        atomicAdd(&g_ax[c.w], a.w * g3);
    }
    grid_sync();   // includes threadfence: all REDGs visible before P2 reads

    // ---- Phase 2: violations + mean ----
    float s = 0.0f;
    const float4* ax4 = reinterpret_cast<const float4*>(g_ax);
    for (int i = tid; i < nc4; i += stride) {
        float4 ax = __ldcg(&ax4[i]);
        float4 rh = rhs4[i];
        int4   sn = sense4[i];
        s += viol(ax.x - rh.x, sn.x);
        s += viol(ax.y - rh.y, sn.y);
        s += viol(ax.z - rh.z, sn.z);
        s += viol(ax.w - rh.w, sn.w);
    }
    #pragma unroll
    for (int off = 16; off > 0; off >>= 1)
        s += __shfl_down_sync(0xFFFFFFFFu, s, off);

    __shared__ float warp_sums[8];
    int lane = threadIdx.x & 31;
    int wid  = threadIdx.x >> 5;
    if (lane == 0) warp_sums[wid] = s;
    __syncthreads();
    if (wid == 0) {
        float t = (lane < 8) ? warp_sums[lane] : 0.0f;
        #pragma unroll
        for (int off = 4; off > 0; off >>= 1)
            t += __shfl_down_sync(0xFFFFFFFFu, t, off);
        if (lane == 0) atomicAdd(out, t * inv_n);
    }
}

// ---------------------------------------------------------------------------
extern "C" void kernel_launch(void* const* d_in, const int* in_sizes, int n_in,
                              void* d_out, int out_size) {
    const float* pred   = (const float*)d_in[0];
    const int*   cidx   = (const int*)  d_in[1];
    const int*   vidx   = (const int*)  d_in[2];
    const float* coeff  = (const float*)d_in[3];
    const float* rhs    = (const float*)d_in[4];
    const int*   sense  = (const int*)  d_in[5];

    int nnz       = in_sizes[1];
    int n_constrs = in_sizes[4];

    float* out = (float*)d_out;

    int nwork = nnz / 4;          // 5,000,000
    int nc4   = n_constrs / 4;    // 250,000

    fused_kernel<<<NBLOCKS, NTHREADS>>>(
        pred,
        reinterpret_cast<const int4*>(cidx),
        reinterpret_cast<const int4*>(vidx),
        reinterpret_cast<const float4*>(coeff),
        reinterpret_cast<const float4*>(rhs),
        reinterpret_cast<const int4*>(sense),
        out, nwork, nc4, 1.0f / (float)n_constrs);
}

// round 12
// speedup vs baseline: 1.0999x; 1.0999x over previous
#include <cuda_runtime.h>
#include <cuda_bf16.h>

// Inputs (metadata order):
// 0: pred float32 [2M]  1: constr_idx int32 [20M]  2: var_idx int32 [20M]
// 3: coeff float32 [20M]  4: constr_rhs float32 [1M]  5: constr_sense int32 [1M]
// Output: scalar float (mean violation)

#define MAX_CONSTRS 1000000
#define SCATTER_BLOCKS 1184   // 148 SMs x 8 blocks -> 64 warps/SM, one wave

__device__ float g_ax[MAX_CONSTRS];

// ---------------------------------------------------------------------------
// scatter: ax[cidx[k]] += coeff[k] * sigmoid(pred[vidx[k]]).
// Grid-stride at exactly full occupancy (one persistent wave, no tail):
// LTS-sector-bound; max resident warps = max outstanding atomics.
// ---------------------------------------------------------------------------
__device__ __forceinline__ float fast_sigmoid(float x) {
    float t;
    asm("tanh.approx.f32 %0, %1;" : "=f"(t) : "f"(0.5f * x));
    return fmaf(0.5f, t, 0.5f);
}

__global__ void __launch_bounds__(256, 8) scatter_kernel(
        const float*  __restrict__ pred,
        const int4*   __restrict__ cidx4,
        const int4*   __restrict__ vidx4,
        const float4* __restrict__ coeff4,
        float* __restrict__ out,
        int nwork) {
    int tid = blockIdx.x * blockDim.x + threadIdx.x;
    if (tid == 0) *out = 0.0f;
    const int stride = SCATTER_BLOCKS * 256;

    for (int i = tid; i < nwork; i += stride) {
        int4   c = __ldcs(&cidx4[i]);
        int4   v = __ldcs(&vidx4[i]);
        float4 a = __ldcs(&coeff4[i]);

        float p0 = __ldcg(&pred[v.x]);
        float p1 = __ldcg(&pred[v.y]);
        float p2 = __ldcg(&pred[v.z]);
        float p3 = __ldcg(&pred[v.w]);

        float g0 = fast_sigmoid(p0);
        float g1 = fast_sigmoid(p1);
        float g2 = fast_sigmoid(p2);
        float g3 = fast_sigmoid(p3);

        atomicAdd(&g_ax[c.x], a.x * g0);
        atomicAdd(&g_ax[c.y], a.y * g1);
        atomicAdd(&g_ax[c.z], a.z * g2);
        atomicAdd(&g_ax[c.w], a.w * g3);
    }
}

// ---------------------------------------------------------------------------
// reduce: violations + mean, 1 float4/thread, 977 blocks (measured-best).
// ---------------------------------------------------------------------------
__device__ __forceinline__ float viol(float diff, int sn) {
    float v1 = fmaxf(diff, 0.0f);
    float v2 = fmaxf(-diff, 0.0f);
    float v3 = fabsf(diff);
    return (sn == 1) ? v1 : (sn == 2) ? v2 : (sn == 3) ? v3 : 0.0f;
}

__global__ void __launch_bounds__(256) reduce_kernel(
        const float4* __restrict__ rhs4,
        const int4*   __restrict__ sense4,
        float* __restrict__ out,
        int n4, float inv_n) {
    float s = 0.0f;
    const float4* ax4 = reinterpret_cast<const float4*>(g_ax);
    int i = blockIdx.x * blockDim.x + threadIdx.x;
    if (i < n4) {
        float4 ax = __ldcg(&ax4[i]);
        float4 rh = rhs4[i];
        int4   sn = sense4[i];
        s += viol(ax.x - rh.x, sn.x);
        s += viol(ax.y - rh.y, sn.y);
        s += viol(ax.z - rh.z, sn.z);
        s += viol(ax.w - rh.w, sn.w);
    }
    #pragma unroll
    for (int off = 16; off > 0; off >>= 1)
        s += __shfl_down_sync(0xFFFFFFFFu, s, off);

    __shared__ float warp_sums[8];
    int lane = threadIdx.x & 31;
    int wid  = threadIdx.x >> 5;
    if (lane == 0) warp_sums[wid] = s;
    __syncthreads();
    if (wid == 0) {
        float t = (lane < 8) ? warp_sums[lane] : 0.0f;
        #pragma unroll
        for (int off = 4; off > 0; off >>= 1)
            t += __shfl_down_sync(0xFFFFFFFFu, t, off);
        if (lane == 0) atomicAdd(out, t * inv_n);
    }
}

// ---------------------------------------------------------------------------
extern "C" void kernel_launch(void* const* d_in, const int* in_sizes, int n_in,
                              void* d_out, int out_size) {
    const float* pred   = (const float*)d_in[0];
    const int*   cidx   = (const int*)  d_in[1];
    const int*   vidx   = (const int*)  d_in[2];
    const float* coeff  = (const float*)d_in[3];
    const float* rhs    = (const float*)d_in[4];
    const int*   sense  = (const int*)  d_in[5];

    int nnz       = in_sizes[1];
    int n_constrs = in_sizes[4];

    float* out = (float*)d_out;

    // 1) zero ax via memset node
    {
        void* ax_ptr = nullptr;
        cudaGetSymbolAddress(&ax_ptr, g_ax);
        cudaMemsetAsync(ax_ptr, 0, (size_t)n_constrs * sizeof(float));
    }

    // 2) scatter: grid-stride, one full-occupancy wave (no tail)
    {
        int nwork = nnz / 4;    // 5,000,000
        scatter_kernel<<<SCATTER_BLOCKS, 256>>>(
            pred,
            reinterpret_cast<const int4*>(cidx),
            reinterpret_cast<const int4*>(vidx),
            reinterpret_cast<const float4*>(coeff),
            out, nwork);
    }

    // 3) violations + mean (1 float4/thread, 977 blocks)
    {
        int n4 = n_constrs / 4;                 // 250,000
        int threads = 256;
        int blocks = (n4 + threads - 1) / threads;   // 977
        reduce_kernel<<<blocks, threads>>>(
            reinterpret_cast<const float4*>(rhs),
            reinterpret_cast<const int4*>(sense),
            out, n4, 1.0f / (float)n_constrs);
    }
}

// round 13
// speedup vs baseline: 1.2625x; 1.1478x over previous
#include <cuda_runtime.h>
#include <cuda_bf16.h>

// Inputs (metadata order):
// 0: pred float32 [2M]  1: constr_idx int32 [20M]  2: var_idx int32 [20M]
// 3: coeff float32 [20M]  4: constr_rhs float32 [1M]  5: constr_sense int32 [1M]
// Output: scalar float (mean violation)
//
// Structure (each component at its measured-best configuration):
//   1) memset node zeroes g_ax                      (~1.5 us)
//   2) one-shot scatter, 4 nnz/thread, 256 thr/blk  (~150.5 us, 93% LTS = floor)
//   3) reduce, 2x float4/thread, 489 blocks         (~5 us)

#define MAX_CONSTRS 1000000

__device__ float g_ax[MAX_CONSTRS];

// ---------------------------------------------------------------------------
// scatter: ax[cidx[k]] += coeff[k] * sigmoid(pred[vidx[k]]), 4 nnz/thread.
// One-shot (no grid-stride): retiring blocks keep fresh front-batched loads
// flowing — measured faster than any persistent/loop variant.
// ---------------------------------------------------------------------------
__device__ __forceinline__ float fast_sigmoid(float x) {
    float t;
    asm("tanh.approx.f32 %0, %1;" : "=f"(t) : "f"(0.5f * x));
    return fmaf(0.5f, t, 0.5f);
}

__global__ void __launch_bounds__(256) scatter_kernel(
        const float*  __restrict__ pred,
        const int4*   __restrict__ cidx4,
        const int4*   __restrict__ vidx4,
        const float4* __restrict__ coeff4,
        float* __restrict__ out,
        int nthreads) {
    int i = blockIdx.x * blockDim.x + threadIdx.x;
    if (i == 0) *out = 0.0f;
    if (i >= nthreads) return;

    int4   c = __ldcs(&cidx4[i]);
    int4   v = __ldcs(&vidx4[i]);
    float4 a = __ldcs(&coeff4[i]);

    float p0 = __ldcg(&pred[v.x]);
    float p1 = __ldcg(&pred[v.y]);
    float p2 = __ldcg(&pred[v.z]);
    float p3 = __ldcg(&pred[v.w]);

    float g0 = fast_sigmoid(p0);
    float g1 = fast_sigmoid(p1);
    float g2 = fast_sigmoid(p2);
    float g3 = fast_sigmoid(p3);

    atomicAdd(&g_ax[c.x], a.x * g0);
    atomicAdd(&g_ax[c.y], a.y * g1);
    atomicAdd(&g_ax[c.z], a.z * g2);
    atomicAdd(&g_ax[c.w], a.w * g3);
}

// ---------------------------------------------------------------------------
// reduce: violations + mean, 2x float4 per thread, 489 blocks, branchless,
// no writeback, no prefetch (both measured as regressions).
// ---------------------------------------------------------------------------
__device__ __forceinline__ float viol(float diff, int sn) {
    float v1 = fmaxf(diff, 0.0f);
    float v2 = fmaxf(-diff, 0.0f);
    float v3 = fabsf(diff);
    return (sn == 1) ? v1 : (sn == 2) ? v2 : (sn == 3) ? v3 : 0.0f;
}

__global__ void __launch_bounds__(256) reduce_kernel(
        const float4* __restrict__ rhs4,
        const int4*   __restrict__ sense4,
        float* __restrict__ out,
        int n4, float inv_n) {
    float s = 0.0f;
    const float4* ax4 = reinterpret_cast<const float4*>(g_ax);
    int i = blockIdx.x * blockDim.x * 2 + threadIdx.x;
    int j = i + blockDim.x;
    if (i < n4) {
        float4 ax0 = __ldcg(&ax4[i]);
        float4 rh0 = __ldcs(&rhs4[i]);
        int4   sn0 = __ldcs(&sense4[i]);
        if (j < n4) {
            float4 ax1 = __ldcg(&ax4[j]);
            float4 rh1 = __ldcs(&rhs4[j]);
            int4   sn1 = __ldcs(&sense4[j]);
            s += viol(ax1.x - rh1.x, sn1.x);
            s += viol(ax1.y - rh1.y, sn1.y);
            s += viol(ax1.z - rh1.z, sn1.z);
            s += viol(ax1.w - rh1.w, sn1.w);
        }
        s += viol(ax0.x - rh0.x, sn0.x);
        s += viol(ax0.y - rh0.y, sn0.y);
        s += viol(ax0.z - rh0.z, sn0.z);
        s += viol(ax0.w - rh0.w, sn0.w);
    }
    #pragma unroll
    for (int off = 16; off > 0; off >>= 1)
        s += __shfl_down_sync(0xFFFFFFFFu, s, off);

    __shared__ float warp_sums[8];
    int lane = threadIdx.x & 31;
    int wid  = threadIdx.x >> 5;
    if (lane == 0) warp_sums[wid] = s;
    __syncthreads();
    if (wid == 0) {
        float t = (lane < 8) ? warp_sums[lane] : 0.0f;
        #pragma unroll
        for (int off = 4; off > 0; off >>= 1)
            t += __shfl_down_sync(0xFFFFFFFFu, t, off);
        if (lane == 0) atomicAdd(out, t * inv_n);
    }
}

// ---------------------------------------------------------------------------
extern "C" void kernel_launch(void* const* d_in, const int* in_sizes, int n_in,
                              void* d_out, int out_size) {
    const float* pred   = (const float*)d_in[0];
    const int*   cidx   = (const int*)  d_in[1];
    const int*   vidx   = (const int*)  d_in[2];
    const float* coeff  = (const float*)d_in[3];
    const float* rhs    = (const float*)d_in[4];
    const int*   sense  = (const int*)  d_in[5];

    int nnz       = in_sizes[1];
    int n_constrs = in_sizes[4];

    float* out = (float*)d_out;

    // 1) zero ax via memset node
    {
        void* ax_ptr = nullptr;
        cudaGetSymbolAddress(&ax_ptr, g_ax);
        cudaMemsetAsync(ax_ptr, 0, (size_t)n_constrs * sizeof(float));
    }

    // 2) one-shot scatter (4 nnz/thread); also zeroes *out
    {
        int nthreads = nnz / 4;   // 5,000,000
        int threads = 256;
        int blocks = (nthreads + threads - 1) / threads;   // 19532
        scatter_kernel<<<blocks, threads>>>(
            pred,
            reinterpret_cast<const int4*>(cidx),
            reinterpret_cast<const int4*>(vidx),
            reinterpret_cast<const float4*>(coeff),
            out, nthreads);
    }

    // 3) violations + mean (2 float4/thread, 489 blocks)
    {
        int n4 = n_constrs / 4;                 // 250,000
        int threads = 256;
        int blocks = (n4 + threads * 2 - 1) / (threads * 2);   // 489
        reduce_kernel<<<blocks, threads>>>(
            reinterpret_cast<const float4*>(rhs),
            reinterpret_cast<const int4*>(sense),
            out, n4, 1.0f / (float)n_constrs);
    }
}